// round 4
// baseline (speedup 1.0000x reference)
#include <cuda_runtime.h>

#define SEQ 400
#define BATCH 8
#define DM 256          // d_model
#define SD 512          // source_dim
#define NDELTA 800      // 799 distinct deltas, padded to 800
#define BS (BATCH*SEQ)          // 3200
#define BSS (BATCH*SEQ*SEQ)     // 1280000

// Scratch (device globals — no allocations allowed)
__device__ float g_W2[SD*DM];        // w_q2 @ w_k2^T          (512x256)
__device__ float g_RT[DM*NDELTA];    // R^T: [d][delta+399]    (256x800)
__device__ float g_Q[BS*DM];         // x @ w_q                (3200x256)
__device__ float g_K[BS*DM];         // x @ w_k
__device__ float g_Q2W[BS*DM];       // x @ W2
__device__ float g_E[BATCH*SEQ*SEQ]; // batched Q K^T          (8x400x400)
__device__ float g_S[BS*NDELTA];     // Q2W @ RT               (3200x800)

// ---------------------------------------------------------------------------
// Generic 64x64 tile SGEMM, 256 threads, 4x4 micro-tile, BK=16.
// NT=false: C[M,N] = A[M,K] @ B[K,N]   (both row-major)
// NT=true : C[M,N] = A[M,K] @ B[N,K]^T (B row-major, N x K)
// Requires K % 16 == 0 (true for 256/512). M, N arbitrary (bounds-checked).
// blockIdx.z batching via element strides.
// ---------------------------------------------------------------------------
template <bool NT>
__global__ __launch_bounds__(256)
void sgemm64(const float* __restrict__ A, const float* __restrict__ B,
             float* __restrict__ C, int M, int N, int K,
             long strideA, long strideB, long strideC)
{
    __shared__ float As[16][68];
    __shared__ float Bs[16][68];

    A += blockIdx.z * strideA;
    B += blockIdx.z * strideB;
    C += blockIdx.z * strideC;

    const int m0 = blockIdx.y * 64;
    const int n0 = blockIdx.x * 64;
    const int tid = threadIdx.x;
    const int tx = tid & 15;
    const int ty = tid >> 4;

    float acc[4][4];
#pragma unroll
    for (int r = 0; r < 4; r++)
#pragma unroll
        for (int c = 0; c < 4; c++) acc[r][c] = 0.f;

    for (int k0 = 0; k0 < K; k0 += 16) {
        // ---- load A tile: As[kk][row] = A[m0+row][k0+kk]
        {
            const int ar = tid >> 2;          // 0..63
            const int ak = (tid & 3) * 4;     // 0,4,8,12
            const int gm = m0 + ar;
            float4 v = make_float4(0.f, 0.f, 0.f, 0.f);
            if (gm < M) v = *(const float4*)(A + (long)gm * K + k0 + ak);
            As[ak + 0][ar] = v.x;
            As[ak + 1][ar] = v.y;
            As[ak + 2][ar] = v.z;
            As[ak + 3][ar] = v.w;
        }
        // ---- load B tile: Bs[kk][col]
        if (NT) {
            // B is N x K: Bs[kk][col] = B[n0+col][k0+kk]
            const int br = tid >> 2;
            const int bk = (tid & 3) * 4;
            const int gn = n0 + br;
            float4 v = make_float4(0.f, 0.f, 0.f, 0.f);
            if (gn < N) v = *(const float4*)(B + (long)gn * K + k0 + bk);
            Bs[bk + 0][br] = v.x;
            Bs[bk + 1][br] = v.y;
            Bs[bk + 2][br] = v.z;
            Bs[bk + 3][br] = v.w;
        } else {
            // B is K x N: Bs[kk][col] = B[k0+kk][n0+col]
            const int bk = tid >> 4;          // 0..15
            const int bc = (tid & 15) * 4;    // 0..60
            const int gn = n0 + bc;
            float4 v = make_float4(0.f, 0.f, 0.f, 0.f);
            const float* brow = B + (long)(k0 + bk) * N;
            if (gn + 3 < N) {
                v = *(const float4*)(brow + gn);
            } else {
                if (gn + 0 < N) v.x = brow[gn + 0];
                if (gn + 1 < N) v.y = brow[gn + 1];
                if (gn + 2 < N) v.z = brow[gn + 2];
                if (gn + 3 < N) v.w = brow[gn + 3];
            }
            *(float4*)&Bs[bk][bc] = v;
        }
        __syncthreads();

#pragma unroll
        for (int kk = 0; kk < 16; kk++) {
            const float4 a = *(const float4*)&As[kk][ty * 4];
            const float4 b = *(const float4*)&Bs[kk][tx * 4];
            acc[0][0] += a.x * b.x; acc[0][1] += a.x * b.y; acc[0][2] += a.x * b.z; acc[0][3] += a.x * b.w;
            acc[1][0] += a.y * b.x; acc[1][1] += a.y * b.y; acc[1][2] += a.y * b.z; acc[1][3] += a.y * b.w;
            acc[2][0] += a.z * b.x; acc[2][1] += a.z * b.y; acc[2][2] += a.z * b.z; acc[2][3] += a.z * b.w;
            acc[3][0] += a.w * b.x; acc[3][1] += a.w * b.y; acc[3][2] += a.w * b.z; acc[3][3] += a.w * b.w;
        }
        __syncthreads();
    }

#pragma unroll
    for (int r = 0; r < 4; r++) {
        const int gm = m0 + ty * 4 + r;
        if (gm >= M) continue;
#pragma unroll
        for (int c = 0; c < 4; c++) {
            const int gn = n0 + tx * 4 + c;
            if (gn < N) C[(long)gm * N + gn] = acc[r][c];
        }
    }
}

// ---------------------------------------------------------------------------
// Build transposed relative table: RT[d][m] = rel_sinusoid[0, i, j, d]
// for any (i,j) with j-i == m-399. rel depends only on delta:
//   delta >= 0 -> (i=0, j=delta)   offset = delta*DM
//   delta <  0 -> (i=-delta, j=0)  offset = (-delta)*SEQ*DM
// m == 799 is padding (zero).
// ---------------------------------------------------------------------------
__global__ void build_rt(const float* __restrict__ rel, float* __restrict__ RT)
{
    const int m = blockIdx.x;     // 0..799
    const int d = threadIdx.x;    // 0..255
    float v = 0.f;
    if (m <= 798) {
        const int delta = m - 399;
        const long off = (delta >= 0) ? (long)delta * DM : (long)(-delta) * SEQ * DM;
        v = rel[off + d];
    }
    RT[(long)d * NDELTA + m] = v;
}

// ---------------------------------------------------------------------------
// out[b,i,j] = (E[b,i,j] + S[b,i, j-i+399]) / sqrt(256)
// second half of out (if present) = mask[b,i] * mask[b,j] as float
// ---------------------------------------------------------------------------
__global__ void combine(const float* __restrict__ E, const float* __restrict__ S,
                        const int* __restrict__ mask, float* __restrict__ out,
                        int out_size)
{
    const int idx = blockIdx.x * blockDim.x + threadIdx.x;
    if (idx >= BSS) return;
    const int j = idx % SEQ;
    const int bi = idx / SEQ;     // b*SEQ + i
    const int i = bi % SEQ;
    const int b = bi / SEQ;

    const float v = (E[idx] + S[(long)bi * NDELTA + (j - i + 399)]) * 0.0625f;
    out[idx] = v;
    if (out_size >= 2 * BSS) {
        out[BSS + idx] = (float)(mask[b * SEQ + i] * mask[b * SEQ + j]);
    }
}

extern "C" void kernel_launch(void* const* d_in, const int* in_sizes, int n_in,
                              void* d_out, int out_size)
{
    const float* x    = (const float*)d_in[0];  // (8,400,512)
    const int*   mask = (const int*)  d_in[1];  // (8,400)
    const float* w_q  = (const float*)d_in[2];  // (512,256)
    const float* w_q2 = (const float*)d_in[3];  // (512,256)
    const float* w_k  = (const float*)d_in[4];  // (512,256)
    const float* w_k2 = (const float*)d_in[5];  // (256,256)
    const float* rel  = (const float*)d_in[6];  // (1,400,400,256)
    float* out = (float*)d_out;

    float *W2, *RT, *Q, *Kb, *Q2W, *E, *S;
    cudaGetSymbolAddress((void**)&W2,  g_W2);
    cudaGetSymbolAddress((void**)&RT,  g_RT);
    cudaGetSymbolAddress((void**)&Q,   g_Q);
    cudaGetSymbolAddress((void**)&Kb,  g_K);
    cudaGetSymbolAddress((void**)&Q2W, g_Q2W);
    cudaGetSymbolAddress((void**)&E,   g_E);
    cudaGetSymbolAddress((void**)&S,   g_S);

    // W2 = w_q2 (512x256) @ w_k2^T (256x256)  -> (512x256)
    sgemm64<true><<<dim3((DM + 63) / 64, (SD + 63) / 64, 1), 256>>>(
        w_q2, w_k2, W2, SD, DM, DM, 0, 0, 0);

    // RT gather
    build_rt<<<NDELTA, DM>>>(rel, RT);

    // Q = x @ w_q ; K = x @ w_k ; Q2W = x @ W2   (3200x512 @ 512x256)
    dim3 gproj((DM + 63) / 64, (BS + 63) / 64, 1);
    sgemm64<false><<<gproj, 256>>>(x, w_q, Q,  BS, DM, SD, 0, 0, 0);
    sgemm64<false><<<gproj, 256>>>(x, w_k, Kb, BS, DM, SD, 0, 0, 0);
    sgemm64<false><<<gproj, 256>>>(x, W2,  Q2W, BS, DM, SD, 0, 0, 0);

    // S = Q2W (3200x256) @ RT (256x800)
    sgemm64<false><<<dim3((NDELTA + 63) / 64, (BS + 63) / 64, 1), 256>>>(
        Q2W, RT, S, BS, NDELTA, DM, 0, 0, 0);

    // E[b] = Q[b] (400x256) @ K[b]^T (400x256)^T, batched over z
    sgemm64<true><<<dim3((SEQ + 63) / 64, (SEQ + 63) / 64, BATCH), 256>>>(
        Q, Kb, E, SEQ, SEQ, DM,
        (long)SEQ * DM, (long)SEQ * DM, (long)SEQ * SEQ);

    // Final combine + mask
    combine<<<(BSS + 255) / 256, 256>>>(E, S, mask, out, out_size);
}

// round 5
// speedup vs baseline: 1.3539x; 1.3539x over previous
#include <cuda_runtime.h>

#define SEQ 400
#define BATCH 8
#define DM 256          // d_model
#define SD 512          // source_dim
#define PW 768          // packed projection width: [Q | K | Q2W]
#define ND2 896         // delta columns padded to multiple of 128 (799 real)
#define BS (BATCH*SEQ)          // 3200
#define BSS (BATCH*SEQ*SEQ)     // 1280000

// Scratch (device globals — no allocations allowed)
__device__ float g_Wcat[SD*PW];      // [w_q | w_k | w_q2@w_k2^T]   (512x768)
__device__ float g_P[BS*PW];         // x @ Wcat                    (3200x768)
__device__ float g_RT[DM*ND2];       // R^T: [d][delta+399]         (256x896)
__device__ float g_S[BS*ND2];        // P[:,512:768] @ RT           (3200x896)

// ---------------------------------------------------------------------------
// pack w_q, w_k into Wcat columns [0:256) and [256:512)
// ---------------------------------------------------------------------------
__global__ void pack_w(const float* __restrict__ wq, const float* __restrict__ wk,
                       float* __restrict__ Wcat)
{
    const int idx = blockIdx.x * blockDim.x + threadIdx.x;   // over SD*DM/4 float4s
    if (idx >= SD * DM / 4) return;
    const int row = idx / (DM / 4);
    const int c4  = idx % (DM / 4);
    const float4 q = ((const float4*)wq)[idx];
    const float4 k = ((const float4*)wk)[idx];
    ((float4*)(Wcat + (long)row * PW))[c4] = q;
    ((float4*)(Wcat + (long)row * PW + DM))[c4] = k;
}

// ---------------------------------------------------------------------------
// W2 = w_q2 (512x256) @ w_k2^T (256x256) written into Wcat cols [512:768)
// 64x64 tile, 4x4 micro, all dims divisible by 64 -> no bounds checks.
// ---------------------------------------------------------------------------
__global__ __launch_bounds__(256)
void w2gemm(const float* __restrict__ A, const float* __restrict__ B,
            float* __restrict__ Wcat)
{
    __shared__ float As[16][68];
    __shared__ float Bs[16][68];
    const int m0 = blockIdx.y * 64, n0 = blockIdx.x * 64;
    const int tid = threadIdx.x, tx = tid & 15, ty = tid >> 4;
    const int ar = tid >> 2, ak = (tid & 3) * 4;
    float acc[4][4] = {};

    for (int k0 = 0; k0 < DM; k0 += 16) {
        float4 v = *(const float4*)(A + (long)(m0 + ar) * DM + k0 + ak);
        As[ak][ar] = v.x; As[ak+1][ar] = v.y; As[ak+2][ar] = v.z; As[ak+3][ar] = v.w;
        float4 w = *(const float4*)(B + (long)(n0 + ar) * DM + k0 + ak);
        Bs[ak][ar] = w.x; Bs[ak+1][ar] = w.y; Bs[ak+2][ar] = w.z; Bs[ak+3][ar] = w.w;
        __syncthreads();
#pragma unroll
        for (int kk = 0; kk < 16; kk++) {
            const float4 a = *(const float4*)&As[kk][ty * 4];
            const float4 b = *(const float4*)&Bs[kk][tx * 4];
            acc[0][0]+=a.x*b.x; acc[0][1]+=a.x*b.y; acc[0][2]+=a.x*b.z; acc[0][3]+=a.x*b.w;
            acc[1][0]+=a.y*b.x; acc[1][1]+=a.y*b.y; acc[1][2]+=a.y*b.z; acc[1][3]+=a.y*b.w;
            acc[2][0]+=a.z*b.x; acc[2][1]+=a.z*b.y; acc[2][2]+=a.z*b.z; acc[2][3]+=a.z*b.w;
            acc[3][0]+=a.w*b.x; acc[3][1]+=a.w*b.y; acc[3][2]+=a.w*b.z; acc[3][3]+=a.w*b.w;
        }
        __syncthreads();
    }
#pragma unroll
    for (int r = 0; r < 4; r++)
#pragma unroll
        for (int c = 0; c < 4; c++)
            Wcat[(long)(m0 + ty*4 + r) * PW + SD + n0 + tx*4 + c] = acc[r][c];
}

// ---------------------------------------------------------------------------
// Build padded transposed relative table: RT[d][m] = rel[delta = m-399],
// m in [0,799); m in [799,896) is zero padding.
//   delta >= 0 -> rel[0, 0, delta, d]   offset = delta*DM
//   delta <  0 -> rel[0, -delta, 0, d]  offset = (-delta)*SEQ*DM
// ---------------------------------------------------------------------------
__global__ void build_rt(const float* __restrict__ rel, float* __restrict__ RT)
{
    const int m = blockIdx.x;     // 0..895
    const int d = threadIdx.x;    // 0..255
    float v = 0.f;
    if (m <= 798) {
        const int delta = m - 399;
        const long off = (delta >= 0) ? (long)delta * DM : (long)(-delta) * SEQ * DM;
        v = rel[off + d];
    }
    RT[(long)d * ND2 + m] = v;
}

// ---------------------------------------------------------------------------
// 128x128 tile SGEMM (NN), 256 threads, 8x8 micro-tile, BK=8, double-buffered.
// Requires M%128==0, N%128==0, K%8==0 (all call sites satisfy this).
// ---------------------------------------------------------------------------
__global__ __launch_bounds__(256, 1)
void sgemm128(const float* __restrict__ A, const float* __restrict__ B,
              float* __restrict__ C, int K, int lda, int ldb, int ldc)
{
    __shared__ float As[2][8][128];
    __shared__ float Bs[2][8][128];

    const int m0 = blockIdx.y * 128;
    const int n0 = blockIdx.x * 128;
    const int tid = threadIdx.x;

    // A loader: each thread owns one float4 along K of one row
    const int arow = tid >> 1;            // 0..127
    const int akq  = (tid & 1) * 4;       // 0 or 4
    const float* aptr = A + (long)(m0 + arow) * lda + akq;

    // B loader: each thread owns one float4 along N of one k-row
    const int brow = tid >> 5;            // 0..7
    const int bcol = (tid & 31) * 4;      // 0..124
    const float* bptr = B + (long)brow * ldb + n0 + bcol;

    const int tx = tid & 15;
    const int ty = tid >> 4;

    float acc[8][8];
#pragma unroll
    for (int r = 0; r < 8; r++)
#pragma unroll
        for (int c = 0; c < 8; c++) acc[r][c] = 0.f;

    // prime stage 0
    float4 va = *(const float4*)aptr;
    float4 vb = *(const float4*)bptr;
    As[0][akq+0][arow] = va.x; As[0][akq+1][arow] = va.y;
    As[0][akq+2][arow] = va.z; As[0][akq+3][arow] = va.w;
    *(float4*)&Bs[0][brow][bcol] = vb;
    __syncthreads();

    int buf = 0;
    for (int k0 = 0; k0 < K; k0 += 8) {
        const bool more = (k0 + 8 < K);
        if (more) {
            va = *(const float4*)(aptr + k0 + 8);
            vb = *(const float4*)(bptr + (long)(k0 + 8) * ldb);
        }
#pragma unroll
        for (int kk = 0; kk < 8; kk++) {
            const float4 a0 = *(const float4*)&As[buf][kk][ty*8];
            const float4 a1 = *(const float4*)&As[buf][kk][ty*8 + 4];
            const float4 b0 = *(const float4*)&Bs[buf][kk][tx*8];
            const float4 b1 = *(const float4*)&Bs[buf][kk][tx*8 + 4];
            const float a[8]  = {a0.x, a0.y, a0.z, a0.w, a1.x, a1.y, a1.z, a1.w};
            const float bb[8] = {b0.x, b0.y, b0.z, b0.w, b1.x, b1.y, b1.z, b1.w};
#pragma unroll
            for (int r = 0; r < 8; r++)
#pragma unroll
                for (int c = 0; c < 8; c++) acc[r][c] += a[r] * bb[c];
        }
        if (more) {
            buf ^= 1;
            As[buf][akq+0][arow] = va.x; As[buf][akq+1][arow] = va.y;
            As[buf][akq+2][arow] = va.z; As[buf][akq+3][arow] = va.w;
            *(float4*)&Bs[buf][brow][bcol] = vb;
            __syncthreads();
        }
    }

#pragma unroll
    for (int r = 0; r < 8; r++) {
        const long row = m0 + ty*8 + r;
        float4 o0 = make_float4(acc[r][0], acc[r][1], acc[r][2], acc[r][3]);
        float4 o1 = make_float4(acc[r][4], acc[r][5], acc[r][6], acc[r][7]);
        *(float4*)(C + row * ldc + n0 + tx*8)     = o0;
        *(float4*)(C + row * ldc + n0 + tx*8 + 4) = o1;
    }
}

// ---------------------------------------------------------------------------
// E[b] = Q[b] @ K[b]^T fused with combine:
//   out[b,i,j] = (E[b,i,j] + S[b,i, j-i+399]) / 16
//   out[BSS + idx] = mask[b,i]*mask[b,j]  (if out_size permits)
// Q = P[:, 0:256), K = P[:, 256:512), row stride PW. 64x64 tile, 4x4 micro.
// ---------------------------------------------------------------------------
__global__ __launch_bounds__(256)
void eqkt_combine(const float* __restrict__ P, const float* __restrict__ S,
                  const int* __restrict__ mask, float* __restrict__ out,
                  int out_size)
{
    __shared__ float As[16][68];
    __shared__ float Bs[16][68];

    const int b = blockIdx.z;
    const float* A  = P + (long)b * SEQ * PW;        // Q
    const float* Bp = P + (long)b * SEQ * PW + DM;   // K

    const int m0 = blockIdx.y * 64;
    const int n0 = blockIdx.x * 64;
    const int tid = threadIdx.x;
    const int tx = tid & 15, ty = tid >> 4;
    const int ar = tid >> 2, ak = (tid & 3) * 4;

    float acc[4][4] = {};

    for (int k0 = 0; k0 < DM; k0 += 16) {
        {
            const int gm = m0 + ar;
            float4 v = make_float4(0.f, 0.f, 0.f, 0.f);
            if (gm < SEQ) v = *(const float4*)(A + (long)gm * PW + k0 + ak);
            As[ak][ar] = v.x; As[ak+1][ar] = v.y; As[ak+2][ar] = v.z; As[ak+3][ar] = v.w;
        }
        {
            const int gn = n0 + ar;
            float4 v = make_float4(0.f, 0.f, 0.f, 0.f);
            if (gn < SEQ) v = *(const float4*)(Bp + (long)gn * PW + k0 + ak);
            Bs[ak][ar] = v.x; Bs[ak+1][ar] = v.y; Bs[ak+2][ar] = v.z; Bs[ak+3][ar] = v.w;
        }
        __syncthreads();
#pragma unroll
        for (int kk = 0; kk < 16; kk++) {
            const float4 a = *(const float4*)&As[kk][ty * 4];
            const float4 bv = *(const float4*)&Bs[kk][tx * 4];
            acc[0][0]+=a.x*bv.x; acc[0][1]+=a.x*bv.y; acc[0][2]+=a.x*bv.z; acc[0][3]+=a.x*bv.w;
            acc[1][0]+=a.y*bv.x; acc[1][1]+=a.y*bv.y; acc[1][2]+=a.y*bv.z; acc[1][3]+=a.y*bv.w;
            acc[2][0]+=a.z*bv.x; acc[2][1]+=a.z*bv.y; acc[2][2]+=a.z*bv.z; acc[2][3]+=a.z*bv.w;
            acc[3][0]+=a.w*bv.x; acc[3][1]+=a.w*bv.y; acc[3][2]+=a.w*bv.z; acc[3][3]+=a.w*bv.w;
        }
        __syncthreads();
    }

    const bool wmask = (out_size >= 2 * BSS);
#pragma unroll
    for (int r = 0; r < 4; r++) {
        const int i = m0 + ty*4 + r;
        if (i >= SEQ) continue;
        const int mi = mask[b * SEQ + i];
        const float* srow = S + (long)(b * SEQ + i) * ND2 + (399 - i);
        const long obase = (long)b * SEQ * SEQ + (long)i * SEQ;
#pragma unroll
        for (int c = 0; c < 4; c++) {
            const int j = n0 + tx*4 + c;
            if (j >= SEQ) continue;
            const float v = (acc[r][c] + srow[j]) * 0.0625f;
            out[obase + j] = v;
            if (wmask) out[BSS + obase + j] = (float)(mi * mask[b * SEQ + j]);
        }
    }
}

extern "C" void kernel_launch(void* const* d_in, const int* in_sizes, int n_in,
                              void* d_out, int out_size)
{
    const float* x    = (const float*)d_in[0];  // (8,400,512)
    const int*   mask = (const int*)  d_in[1];  // (8,400)
    const float* w_q  = (const float*)d_in[2];  // (512,256)
    const float* w_q2 = (const float*)d_in[3];  // (512,256)
    const float* w_k  = (const float*)d_in[4];  // (512,256)
    const float* w_k2 = (const float*)d_in[5];  // (256,256)
    const float* rel  = (const float*)d_in[6];  // (1,400,400,256)
    float* out = (float*)d_out;

    float *Wcat, *P, *RT, *S;
    cudaGetSymbolAddress((void**)&Wcat, g_Wcat);
    cudaGetSymbolAddress((void**)&P,    g_P);
    cudaGetSymbolAddress((void**)&RT,   g_RT);
    cudaGetSymbolAddress((void**)&S,    g_S);

    // 1) Pack w_q, w_k into Wcat
    pack_w<<<(SD * DM / 4 + 255) / 256, 256>>>(w_q, w_k, Wcat);

    // 2) W2 = w_q2 @ w_k2^T -> Wcat cols [512:768)
    w2gemm<<<dim3(DM / 64, SD / 64), 256>>>(w_q2, w_k2, Wcat);

    // 3) Relative table gather (padded to 896 cols)
    build_rt<<<ND2, DM>>>(rel, RT);

    // 4) P = x @ Wcat  (3200x768x512)
    sgemm128<<<dim3(PW / 128, BS / 128), 256>>>(x, Wcat, P, SD, SD, PW, PW);

    // 5) S = P[:,512:768) @ RT  (3200x896x256)
    sgemm128<<<dim3(ND2 / 128, BS / 128), 256>>>(P + SD, RT, S, DM, PW, ND2, ND2);

    // 6) out = (Q K^T + gather(S)) / 16, plus mask output
    eqkt_combine<<<dim3((SEQ + 63) / 64, (SEQ + 63) / 64, BATCH), 256>>>(
        P, S, mask, out, out_size);
}

// round 6
// speedup vs baseline: 1.6505x; 1.2191x over previous
#include <cuda_runtime.h>
#include <cstdint>

#define SEQ 400
#define BATCH 8
#define DM 256          // d_model
#define SD 512          // source_dim
#define PW 768          // packed projection width: [Q | K | Q2W]
#define ND2 896         // delta columns padded (799 real)
#define BS (BATCH*SEQ)          // 3200
#define BSS (BATCH*SEQ*SEQ)     // 1280000

// Scratch (device globals — no allocations allowed)
__device__ float g_Wcat[SD*PW];      // [w_q | w_k | w_q2@w_k2^T]   (512x768)
__device__ float g_P[BS*PW];         // x @ Wcat                    (3200x768)
__device__ float g_RT[DM*ND2];       // R^T: [d][delta+399]         (256x896)
__device__ float g_S[BS*ND2];        // P[:,512:768] @ RT           (3200x896)

// ---------------------------------------------------------------------------
__device__ __forceinline__ float f2tf32(float f) {
    uint32_t u;
    asm("cvt.rna.tf32.f32 %0, %1;" : "=r"(u) : "f"(f));
    return __uint_as_float(u);
}

__device__ __forceinline__ void mma8(float c[4], const uint32_t a[4], const uint32_t b[2]) {
    asm volatile("mma.sync.aligned.m16n8k8.row.col.f32.tf32.tf32.f32 "
        "{%0,%1,%2,%3}, {%4,%5,%6,%7}, {%8,%9}, {%0,%1,%2,%3};"
        : "+f"(c[0]), "+f"(c[1]), "+f"(c[2]), "+f"(c[3])
        : "r"(a[0]), "r"(a[1]), "r"(a[2]), "r"(a[3]), "r"(b[0]), "r"(b[1]));
}

// ---------------------------------------------------------------------------
// pack w_q, w_k into Wcat columns [0:256) and [256:512)
// ---------------------------------------------------------------------------
__global__ void pack_w(const float* __restrict__ wq, const float* __restrict__ wk,
                       float* __restrict__ Wcat)
{
    const int idx = blockIdx.x * blockDim.x + threadIdx.x;
    if (idx >= SD * DM / 4) return;
    const int row = idx / (DM / 4);
    const int c4  = idx % (DM / 4);
    const float4 q = ((const float4*)wq)[idx];
    const float4 k = ((const float4*)wk)[idx];
    ((float4*)(Wcat + (long)row * PW))[c4] = q;
    ((float4*)(Wcat + (long)row * PW + DM))[c4] = k;
}

// ---------------------------------------------------------------------------
// W2 = w_q2 (512x256) @ w_k2^T (256x256) -> Wcat cols [512:768). fp32 SIMT
// (kept full precision: this output feeds two further tf32 GEMMs).
// ---------------------------------------------------------------------------
__global__ __launch_bounds__(256)
void w2gemm(const float* __restrict__ A, const float* __restrict__ B,
            float* __restrict__ Wcat)
{
    __shared__ float As[16][68];
    __shared__ float Bs[16][68];
    const int m0 = blockIdx.y * 64, n0 = blockIdx.x * 64;
    const int tid = threadIdx.x, tx = tid & 15, ty = tid >> 4;
    const int ar = tid >> 2, ak = (tid & 3) * 4;
    float acc[4][4] = {};

    for (int k0 = 0; k0 < DM; k0 += 16) {
        float4 v = *(const float4*)(A + (long)(m0 + ar) * DM + k0 + ak);
        As[ak][ar] = v.x; As[ak+1][ar] = v.y; As[ak+2][ar] = v.z; As[ak+3][ar] = v.w;
        float4 w = *(const float4*)(B + (long)(n0 + ar) * DM + k0 + ak);
        Bs[ak][ar] = w.x; Bs[ak+1][ar] = w.y; Bs[ak+2][ar] = w.z; Bs[ak+3][ar] = w.w;
        __syncthreads();
#pragma unroll
        for (int kk = 0; kk < 16; kk++) {
            const float4 a = *(const float4*)&As[kk][ty * 4];
            const float4 b = *(const float4*)&Bs[kk][tx * 4];
            acc[0][0]+=a.x*b.x; acc[0][1]+=a.x*b.y; acc[0][2]+=a.x*b.z; acc[0][3]+=a.x*b.w;
            acc[1][0]+=a.y*b.x; acc[1][1]+=a.y*b.y; acc[1][2]+=a.y*b.z; acc[1][3]+=a.y*b.w;
            acc[2][0]+=a.z*b.x; acc[2][1]+=a.z*b.y; acc[2][2]+=a.z*b.z; acc[2][3]+=a.z*b.w;
            acc[3][0]+=a.w*b.x; acc[3][1]+=a.w*b.y; acc[3][2]+=a.w*b.z; acc[3][3]+=a.w*b.w;
        }
        __syncthreads();
    }
#pragma unroll
    for (int r = 0; r < 4; r++)
#pragma unroll
        for (int c = 0; c < 4; c++)
            Wcat[(long)(m0 + ty*4 + r) * PW + SD + n0 + tx*4 + c] = acc[r][c];
}

// ---------------------------------------------------------------------------
// Build padded transposed relative table (see round-4 comment).
// ---------------------------------------------------------------------------
__global__ void build_rt(const float* __restrict__ rel, float* __restrict__ RT)
{
    const int m = blockIdx.x;     // 0..895
    const int d = threadIdx.x;    // 0..255
    float v = 0.f;
    if (m <= 798) {
        const int delta = m - 399;
        const long off = (delta >= 0) ? (long)delta * DM : (long)(-delta) * SEQ * DM;
        v = rel[off + d];
    }
    RT[(long)d * ND2 + m] = v;
}

// ---------------------------------------------------------------------------
// tf32 tensor-core GEMM. 128x128 block, BK=16, 256 threads (8 warps, each
// warp owns 64x32 via 4x4 m16n8k8 mma tiles). Double-buffered smem in
// fragment-shuffled layout: compute fetches whole fragments with one
// LDS.128 (A) / LDS.64 (B), conflict-free.
//
// NTB=false: C = A[M,K] @ B[K,N]        (both row-major)
// NTB=true : C = A[M,K] @ B[N,K]^T      (B row-major N x K)
// ECOMB=true: fused epilogue  out[b,i,j] = (acc + S[b,i,j-i+399])/16,
//             mask product to out[BSS+...]; bounds Mreal/Nreal apply.
// Requires: K%16==0; for ECOMB=false additionally M%128==0, N%128==0.
// ---------------------------------------------------------------------------
template <bool NTB, bool ECOMB>
__global__ __launch_bounds__(256)
void mma_tf32(const float* __restrict__ A, const float* __restrict__ B,
              float* __restrict__ C,
              int Mreal, int Nreal, int K, int lda, int ldb, int ldc,
              long sA, long sB,
              const float* __restrict__ S, const int* __restrict__ mask,
              float* __restrict__ out, int out_size)
{
    __shared__ float As[2][2048];   // [k_half(2)][m_tile(8)][lane(32)][slot(4)]
    __shared__ float Bs[2][2048];   // [k_half(2)][n_tile(16)][lane(32)][slot(2)]

    const int tid  = threadIdx.x;
    const int lane = tid & 31;
    const int wid  = tid >> 5;
    const int wm   = wid >> 2;      // 0..1 -> 64-row half
    const int wn   = wid & 3;       // 0..3 -> 32-col quarter
    const int m0   = blockIdx.y * 128;
    const int n0   = blockIdx.x * 128;

    A += blockIdx.z * sA;
    B += blockIdx.z * sB;

    // ---- A loader: 2 float4 per thread per stage (rows m0.., 16 k-cols)
    int arow[2], acb[2], abase[2];
    const float* aptr[2];
    bool aok[2];
#pragma unroll
    for (int i = 0; i < 2; i++) {
        const int s = tid * 2 + i;        // 0..511
        arow[i] = s >> 2;                 // 0..127
        acb[i]  = (s & 3) * 4;            // 0,4,8,12
        abase[i] = (((acb[i] >> 3) * 8 + (arow[i] >> 4)) * 32 + (arow[i] & 7) * 4) * 4
                 + ((arow[i] >> 3) & 1) + 2 * ((acb[i] >> 2) & 1);
        aok[i]  = (m0 + arow[i]) < Mreal;
        aptr[i] = A + (long)(m0 + arow[i]) * lda + acb[i];
    }

    // ---- B loader: 2 float4 per thread per stage
    int bbase[2];
    const float* bptr[2];
    bool bok[2];
#pragma unroll
    for (int i = 0; i < 2; i++) {
        const int s = tid * 2 + i;
        if (NTB) {
            const int n  = s >> 2;        // 0..127
            const int kb = (s & 3) * 4;   // 0,4,8,12
            bbase[i] = (((kb >> 3) * 16 + (n >> 3)) * 32 + (n & 7) * 4) * 2
                     + ((kb >> 2) & 1);
            bok[i]  = (n0 + n) < Nreal;
            bptr[i] = B + (long)(n0 + n) * ldb + kb;
        } else {
            const int k  = s >> 5;        // 0..15
            const int nb = (s & 31) * 4;  // 0..124
            bbase[i] = (((k >> 3) * 16 + (nb >> 3)) * 32 + (nb & 7) * 4 + (k & 3)) * 2
                     + ((k >> 2) & 1);
            bok[i]  = true;
            bptr[i] = B + (long)k * ldb + n0 + nb;
        }
    }

    float acc[4][4][4];
#pragma unroll
    for (int mt = 0; mt < 4; mt++)
#pragma unroll
        for (int nt = 0; nt < 4; nt++)
#pragma unroll
            for (int r = 0; r < 4; r++) acc[mt][nt][r] = 0.f;

    const float4 z4 = make_float4(0.f, 0.f, 0.f, 0.f);
    float4 av[2], bv[2];

    // prime stage 0 (k0 = 0)
#pragma unroll
    for (int i = 0; i < 2; i++) {
        av[i] = aok[i] ? *(const float4*)(aptr[i]) : z4;
        bv[i] = bok[i] ? *(const float4*)(bptr[i]) : z4;
    }
#pragma unroll
    for (int i = 0; i < 2; i++) {
        As[0][abase[i] + 0]  = f2tf32(av[i].x);
        As[0][abase[i] + 4]  = f2tf32(av[i].y);
        As[0][abase[i] + 8]  = f2tf32(av[i].z);
        As[0][abase[i] + 12] = f2tf32(av[i].w);
        const int st = NTB ? 2 : 8;
        Bs[0][bbase[i] + 0*st] = f2tf32(bv[i].x);
        Bs[0][bbase[i] + 1*st] = f2tf32(bv[i].y);
        Bs[0][bbase[i] + 2*st] = f2tf32(bv[i].z);
        Bs[0][bbase[i] + 3*st] = f2tf32(bv[i].w);
    }
    __syncthreads();

    const int nk = K >> 4;
    int buf = 0;
    for (int kt = 0; kt < nk; kt++) {
        const bool more = (kt + 1 < nk);
        const int knext = (kt + 1) << 4;
        if (more) {
#pragma unroll
            for (int i = 0; i < 2; i++) {
                av[i] = aok[i] ? *(const float4*)(aptr[i] + knext) : z4;
                if (NTB) bv[i] = bok[i] ? *(const float4*)(bptr[i] + knext) : z4;
                else     bv[i] = *(const float4*)(bptr[i] + (long)knext * ldb);
            }
        }

#pragma unroll
        for (int h = 0; h < 2; h++) {
            uint32_t af[4][4];
            uint32_t bf[4][2];
#pragma unroll
            for (int mt = 0; mt < 4; mt++)
                *(uint4*)af[mt] =
                    *(const uint4*)&As[buf][((h * 8 + wm * 4 + mt) * 32 + lane) * 4];
#pragma unroll
            for (int nt = 0; nt < 4; nt++)
                *(uint2*)bf[nt] =
                    *(const uint2*)&Bs[buf][((h * 16 + wn * 4 + nt) * 32 + lane) * 2];
#pragma unroll
            for (int mt = 0; mt < 4; mt++)
#pragma unroll
                for (int nt = 0; nt < 4; nt++)
                    mma8(acc[mt][nt], af[mt], bf[nt]);
        }

        if (more) {
            const int nb = buf ^ 1;
#pragma unroll
            for (int i = 0; i < 2; i++) {
                As[nb][abase[i] + 0]  = f2tf32(av[i].x);
                As[nb][abase[i] + 4]  = f2tf32(av[i].y);
                As[nb][abase[i] + 8]  = f2tf32(av[i].z);
                As[nb][abase[i] + 12] = f2tf32(av[i].w);
                const int st = NTB ? 2 : 8;
                Bs[nb][bbase[i] + 0*st] = f2tf32(bv[i].x);
                Bs[nb][bbase[i] + 1*st] = f2tf32(bv[i].y);
                Bs[nb][bbase[i] + 2*st] = f2tf32(bv[i].z);
                Bs[nb][bbase[i] + 3*st] = f2tf32(bv[i].w);
            }
            __syncthreads();
            buf = nb;
        }
    }

    // ---- epilogue ----
    if (!ECOMB) {
#pragma unroll
        for (int mt = 0; mt < 4; mt++) {
            const int r0 = m0 + wm * 64 + mt * 16 + (lane >> 2);
            const int r1 = r0 + 8;
#pragma unroll
            for (int nt = 0; nt < 4; nt++) {
                const int c = n0 + wn * 32 + nt * 8 + (lane & 3) * 2;
                *(float2*)&C[(long)r0 * ldc + c] = make_float2(acc[mt][nt][0], acc[mt][nt][1]);
                *(float2*)&C[(long)r1 * ldc + c] = make_float2(acc[mt][nt][2], acc[mt][nt][3]);
            }
        }
    } else {
        const int b = blockIdx.z;
        const bool wmask = (out_size >= 2 * BSS);
#pragma unroll
        for (int mt = 0; mt < 4; mt++) {
            const int ibase = m0 + wm * 64 + mt * 16 + (lane >> 2);
#pragma unroll
            for (int half = 0; half < 2; half++) {
                const int i = ibase + half * 8;
                if (i >= SEQ) continue;
                const int mi = mask[b * SEQ + i];
                const float* srow = S + (long)(b * SEQ + i) * ND2 + (399 - i);
                const long obase = (long)b * SEQ * SEQ + (long)i * SEQ;
#pragma unroll
                for (int nt = 0; nt < 4; nt++) {
                    const int c = n0 + wn * 32 + nt * 8 + (lane & 3) * 2;
#pragma unroll
                    for (int e = 0; e < 2; e++) {
                        const int j = c + e;
                        if (j >= SEQ) continue;
                        const float v = (acc[mt][nt][half * 2 + e] + srow[j]) * 0.0625f;
                        out[obase + j] = v;
                        if (wmask) out[BSS + obase + j] = (float)(mi * mask[b * SEQ + j]);
                    }
                }
            }
        }
    }
}

extern "C" void kernel_launch(void* const* d_in, const int* in_sizes, int n_in,
                              void* d_out, int out_size)
{
    const float* x    = (const float*)d_in[0];  // (8,400,512)
    const int*   mask = (const int*)  d_in[1];  // (8,400)
    const float* w_q  = (const float*)d_in[2];  // (512,256)
    const float* w_q2 = (const float*)d_in[3];  // (512,256)
    const float* w_k  = (const float*)d_in[4];  // (512,256)
    const float* w_k2 = (const float*)d_in[5];  // (256,256)
    const float* rel  = (const float*)d_in[6];  // (1,400,400,256)
    float* out = (float*)d_out;

    float *Wcat, *P, *RT, *S;
    cudaGetSymbolAddress((void**)&Wcat, g_Wcat);
    cudaGetSymbolAddress((void**)&P,    g_P);
    cudaGetSymbolAddress((void**)&RT,   g_RT);
    cudaGetSymbolAddress((void**)&S,    g_S);

    // 1) Pack w_q, w_k into Wcat
    pack_w<<<(SD * DM / 4 + 255) / 256, 256>>>(w_q, w_k, Wcat);

    // 2) W2 = w_q2 @ w_k2^T -> Wcat cols [512:768)  (fp32)
    w2gemm<<<dim3(DM / 64, SD / 64), 256>>>(w_q2, w_k2, Wcat);

    // 3) Relative table gather (padded to 896 cols)
    build_rt<<<ND2, DM>>>(rel, RT);

    // 4) P = x @ Wcat  (3200x768x512), tf32
    mma_tf32<false, false><<<dim3(PW / 128, BS / 128), 256>>>(
        x, Wcat, P, BS, PW, SD, SD, PW, PW, 0, 0,
        nullptr, nullptr, nullptr, 0);

    // 5) S = P[:,512:768) @ RT  (3200x896x256), tf32
    mma_tf32<false, false><<<dim3(ND2 / 128, BS / 128), 256>>>(
        P + SD, RT, S, BS, ND2, DM, PW, ND2, ND2, 0, 0,
        nullptr, nullptr, nullptr, 0);

    // 6) E = Q @ K^T fused with combine + mask, tf32 NT, batched over z
    mma_tf32<true, true><<<dim3(4, 4, BATCH), 256>>>(
        P, P + DM, nullptr, SEQ, SEQ, DM, PW, PW, 0,
        (long)SEQ * PW, (long)SEQ * PW,
        S, mask, out, out_size);
}

// round 7
// speedup vs baseline: 2.1682x; 1.3137x over previous
#include <cuda_runtime.h>
#include <cstdint>

#define SEQ 400
#define BATCH 8
#define DM 256          // d_model
#define SD 512          // source_dim
#define PW 768          // packed projection width: [Q | K | Q2W]
#define ND2 896         // delta columns padded (799 real)
#define BS (BATCH*SEQ)          // 3200
#define BSS (BATCH*SEQ*SEQ)     // 1280000

// Scratch (device globals — no allocations allowed)
__device__ float g_Xt[BS*SD];        // tf32-rounded x              (3200x512)
__device__ float g_Wcat[SD*PW];      // [w_q | w_k | w_q2@w_k2^T]   (512x768) tf32
__device__ float g_P[BS*PW];         // Xt @ Wcat                   (3200x768) tf32
__device__ float g_RT[DM*ND2];       // R^T: [d][delta+399]         (256x896) tf32
__device__ float g_S[BS*ND2];        // P[:,512:768] @ RT           (3200x896) fp32

// ---------------------------------------------------------------------------
__device__ __forceinline__ float f2tf32(float f) {
    uint32_t u;
    asm("cvt.rna.tf32.f32 %0, %1;" : "=r"(u) : "f"(f));
    return __uint_as_float(u);
}

__device__ __forceinline__ void mma8(float c[4], const uint32_t a[4], const uint32_t b[2]) {
    asm volatile("mma.sync.aligned.m16n8k8.row.col.f32.tf32.tf32.f32 "
        "{%0,%1,%2,%3}, {%4,%5,%6,%7}, {%8,%9}, {%0,%1,%2,%3};"
        : "+f"(c[0]), "+f"(c[1]), "+f"(c[2]), "+f"(c[3])
        : "r"(a[0]), "r"(a[1]), "r"(a[2]), "r"(a[3]), "r"(b[0]), "r"(b[1]));
}

__device__ __forceinline__ void cpa16(uint32_t dst, const float* src, bool p) {
    asm volatile("cp.async.cg.shared.global [%0], [%1], 16, %2;"
                 :: "r"(dst), "l"(src), "r"(p ? 16 : 0));
}
__device__ __forceinline__ void cpa_commit() {
    asm volatile("cp.async.commit_group;");
}
__device__ __forceinline__ void cpa_wait0() {
    asm volatile("cp.async.wait_group 0;");
}

// ---------------------------------------------------------------------------
// tf32-round x into g_Xt
// ---------------------------------------------------------------------------
__global__ void conv_x(const float* __restrict__ x, float* __restrict__ Xt)
{
    const int idx = blockIdx.x * blockDim.x + threadIdx.x;
    if (idx >= BS * SD / 4) return;
    float4 v = ((const float4*)x)[idx];
    v.x = f2tf32(v.x); v.y = f2tf32(v.y); v.z = f2tf32(v.z); v.w = f2tf32(v.w);
    ((float4*)Xt)[idx] = v;
}

// ---------------------------------------------------------------------------
// pack w_q, w_k (tf32-rounded) into Wcat columns [0:256) and [256:512)
// ---------------------------------------------------------------------------
__global__ void pack_w(const float* __restrict__ wq, const float* __restrict__ wk,
                       float* __restrict__ Wcat)
{
    const int idx = blockIdx.x * blockDim.x + threadIdx.x;
    if (idx >= SD * DM / 4) return;
    const int row = idx / (DM / 4);
    const int c4  = idx % (DM / 4);
    float4 q = ((const float4*)wq)[idx];
    float4 k = ((const float4*)wk)[idx];
    q.x = f2tf32(q.x); q.y = f2tf32(q.y); q.z = f2tf32(q.z); q.w = f2tf32(q.w);
    k.x = f2tf32(k.x); k.y = f2tf32(k.y); k.z = f2tf32(k.z); k.w = f2tf32(k.w);
    ((float4*)(Wcat + (long)row * PW))[c4] = q;
    ((float4*)(Wcat + (long)row * PW + DM))[c4] = k;
}

// ---------------------------------------------------------------------------
// W2 = w_q2 (512x256) @ w_k2^T (256x256) -> Wcat cols [512:768).
// fp32 SIMT inner product (full precision), tf32-rounded on store.
// ---------------------------------------------------------------------------
__global__ __launch_bounds__(256)
void w2gemm(const float* __restrict__ A, const float* __restrict__ B,
            float* __restrict__ Wcat)
{
    __shared__ float As[16][68];
    __shared__ float Bs[16][68];
    const int m0 = blockIdx.y * 64, n0 = blockIdx.x * 64;
    const int tid = threadIdx.x, tx = tid & 15, ty = tid >> 4;
    const int ar = tid >> 2, ak = (tid & 3) * 4;
    float acc[4][4] = {};

    for (int k0 = 0; k0 < DM; k0 += 16) {
        float4 v = *(const float4*)(A + (long)(m0 + ar) * DM + k0 + ak);
        As[ak][ar] = v.x; As[ak+1][ar] = v.y; As[ak+2][ar] = v.z; As[ak+3][ar] = v.w;
        float4 w = *(const float4*)(B + (long)(n0 + ar) * DM + k0 + ak);
        Bs[ak][ar] = w.x; Bs[ak+1][ar] = w.y; Bs[ak+2][ar] = w.z; Bs[ak+3][ar] = w.w;
        __syncthreads();
#pragma unroll
        for (int kk = 0; kk < 16; kk++) {
            const float4 a = *(const float4*)&As[kk][ty * 4];
            const float4 b = *(const float4*)&Bs[kk][tx * 4];
            acc[0][0]+=a.x*b.x; acc[0][1]+=a.x*b.y; acc[0][2]+=a.x*b.z; acc[0][3]+=a.x*b.w;
            acc[1][0]+=a.y*b.x; acc[1][1]+=a.y*b.y; acc[1][2]+=a.y*b.z; acc[1][3]+=a.y*b.w;
            acc[2][0]+=a.z*b.x; acc[2][1]+=a.z*b.y; acc[2][2]+=a.z*b.z; acc[2][3]+=a.z*b.w;
            acc[3][0]+=a.w*b.x; acc[3][1]+=a.w*b.y; acc[3][2]+=a.w*b.z; acc[3][3]+=a.w*b.w;
        }
        __syncthreads();
    }
#pragma unroll
    for (int r = 0; r < 4; r++)
#pragma unroll
        for (int c = 0; c < 4; c++)
            Wcat[(long)(m0 + ty*4 + r) * PW + SD + n0 + tx*4 + c] = f2tf32(acc[r][c]);
}

// ---------------------------------------------------------------------------
// Build padded transposed relative table (tf32-rounded).
// ---------------------------------------------------------------------------
__global__ void build_rt(const float* __restrict__ rel, float* __restrict__ RT)
{
    const int m = blockIdx.x;     // 0..895
    const int d = threadIdx.x;    // 0..255
    float v = 0.f;
    if (m <= 798) {
        const int delta = m - 399;
        const long off = (delta >= 0) ? (long)delta * DM : (long)(-delta) * SEQ * DM;
        v = f2tf32(rel[off + d]);
    }
    RT[(long)d * ND2 + m] = v;
}

// ---------------------------------------------------------------------------
// tf32 tensor-core GEMM v2. 128x128 block, BK=16, 256 threads (8 warps,
// 64x32 warp tiles, 4x4 m16n8k8 per half-k). Inputs must already be
// tf32-rounded. cp.async (zfill for bounds) into row-major padded smem
// (A rows pad 20, B-NN rows pad 136, B-NT rows pad 20 — all fragment LDS.32
// and cp.async write wavefronts verified conflict-free). Double-buffered.
//
// NTB=false: C = A[M,K] @ B[K,N] (row-major); requires M%128==0, N%128==0.
// NTB=true : C = A[M,K] @ B[N,K]^T; M,N bounded by Mreal/Nreal (zfill).
// ECOMB: fused epilogue out = (acc + gather(S))/16 plus mask output.
// OTF: tf32-round C on store.
// ---------------------------------------------------------------------------
template <bool NTB, bool ECOMB, bool OTF>
__global__ __launch_bounds__(256)
void mmaT(const float* __restrict__ A, const float* __restrict__ B,
          float* __restrict__ C,
          int Mreal, int Nreal, int K, int lda, int ldb, int ldc,
          long sA, long sB,
          const float* __restrict__ S, const int* __restrict__ mask,
          float* __restrict__ out, int out_size)
{
    constexpr int BR = NTB ? 128 : 16;
    constexpr int BC = NTB ? 20 : 136;
    __shared__ float As[2][128][20];
    __shared__ float Bs[2][BR][BC];

    const int tid  = threadIdx.x;
    const int lane = tid & 31;
    const int wid  = tid >> 5;
    const int wm   = wid >> 2;      // 0..1
    const int wn   = wid & 3;       // 0..3
    const int m0   = blockIdx.y * 128;
    const int n0   = blockIdx.x * 128;

    A += blockIdx.z * sA;
    B += blockIdx.z * sB;

    const uint32_t uA = (uint32_t)__cvta_generic_to_shared(&As[0][0][0]);
    const uint32_t uB = (uint32_t)__cvta_generic_to_shared(&Bs[0][0][0]);

    // ---- A loader: arow = tid&127, two float4s at k-offsets ak0, ak0+4
    const int arow = tid & 127;
    const int ak0  = (tid >> 7) * 8;
    const bool aok = (m0 + arow) < Mreal;
    const float* aptr = A + (long)(aok ? (m0 + arow) : 0) * lda + ak0;
    const uint32_t adst = uA + (uint32_t)(arow * 20 + ak0) * 4;

    // ---- B loader
    int bi0, bi1;               // smem float offsets for the two float4s
    const float* bptr;
    long bstep1;                // global float offset between the two float4s
    bool bok = true;
    if (NTB) {
        const int brow = tid & 127;
        const int bk0  = (tid >> 7) * 8;
        bok  = (n0 + brow) < Nreal;
        bptr = B + (long)(bok ? (n0 + brow) : 0) * ldb + bk0;
        bstep1 = 4;
        bi0 = brow * 20 + bk0;
        bi1 = bi0 + 4;
    } else {
        const int bn  = (tid & 31) * 4;
        const int bk0 = tid >> 5;       // 0..7 ; second row bk0+8
        bptr = B + (long)bk0 * ldb + n0 + bn;
        bstep1 = (long)8 * ldb;
        bi0 = bk0 * BC + bn;
        bi1 = (bk0 + 8) * BC + bn;
    }

    float acc[4][4][4];
#pragma unroll
    for (int mt = 0; mt < 4; mt++)
#pragma unroll
        for (int nt = 0; nt < 4; nt++)
#pragma unroll
            for (int r = 0; r < 4; r++) acc[mt][nt][r] = 0.f;

    auto load_stage = [&](int buf, int k0) {
        const uint32_t ao = (uint32_t)buf * (128 * 20 * 4);
        const uint32_t bo = (uint32_t)buf * (BR * BC * 4);
        cpa16(adst + ao,      aptr + k0,     aok);
        cpa16(adst + ao + 16, aptr + k0 + 4, aok);
        if (NTB) {
            cpa16(uB + bo + (uint32_t)bi0 * 4, bptr + k0,          bok);
            cpa16(uB + bo + (uint32_t)bi1 * 4, bptr + k0 + bstep1, bok);
        } else {
            cpa16(uB + bo + (uint32_t)bi0 * 4, bptr + (long)k0 * ldb,          true);
            cpa16(uB + bo + (uint32_t)bi1 * 4, bptr + (long)k0 * ldb + bstep1, true);
        }
        cpa_commit();
    };

    load_stage(0, 0);
    cpa_wait0();
    __syncthreads();

    const int nk = K >> 4;
    int buf = 0;
    for (int kt = 0; kt < nk; kt++) {
        const bool more = (kt + 1 < nk);
        if (more) load_stage(buf ^ 1, (kt + 1) << 4);

#pragma unroll
        for (int h = 0; h < 2; h++) {
            const int c = h * 8 + (lane & 3);
            uint32_t af[4][4];
            uint32_t bf[4][2];
            const float* abase = &As[buf][wm * 64 + (lane >> 2)][c];
#pragma unroll
            for (int mt = 0; mt < 4; mt++) {
                af[mt][0] = __float_as_uint(abase[(mt * 16    ) * 20    ]);
                af[mt][1] = __float_as_uint(abase[(mt * 16 + 8) * 20    ]);
                af[mt][2] = __float_as_uint(abase[(mt * 16    ) * 20 + 4]);
                af[mt][3] = __float_as_uint(abase[(mt * 16 + 8) * 20 + 4]);
            }
#pragma unroll
            for (int nt = 0; nt < 4; nt++) {
                const int nB = wn * 32 + nt * 8 + (lane >> 2);
                if (NTB) {
                    bf[nt][0] = __float_as_uint(Bs[buf][nB][c]);
                    bf[nt][1] = __float_as_uint(Bs[buf][nB][c + 4]);
                } else {
                    bf[nt][0] = __float_as_uint(Bs[buf][c][nB]);
                    bf[nt][1] = __float_as_uint(Bs[buf][c + 4][nB]);
                }
            }
#pragma unroll
            for (int mt = 0; mt < 4; mt++)
#pragma unroll
                for (int nt = 0; nt < 4; nt++)
                    mma8(acc[mt][nt], af[mt], bf[nt]);
        }

        if (more) {
            cpa_wait0();
            __syncthreads();
            buf ^= 1;
        }
    }

    // ---- epilogue ----
    if (!ECOMB) {
#pragma unroll
        for (int mt = 0; mt < 4; mt++) {
            const int r0 = m0 + wm * 64 + mt * 16 + (lane >> 2);
            const int r1 = r0 + 8;
#pragma unroll
            for (int nt = 0; nt < 4; nt++) {
                const int cc = n0 + wn * 32 + nt * 8 + (lane & 3) * 2;
                float v0 = acc[mt][nt][0], v1 = acc[mt][nt][1];
                float v2 = acc[mt][nt][2], v3 = acc[mt][nt][3];
                if (OTF) { v0 = f2tf32(v0); v1 = f2tf32(v1); v2 = f2tf32(v2); v3 = f2tf32(v3); }
                *(float2*)&C[(long)r0 * ldc + cc] = make_float2(v0, v1);
                *(float2*)&C[(long)r1 * ldc + cc] = make_float2(v2, v3);
            }
        }
    } else {
        const int b = blockIdx.z;
        const bool wmask = (out_size >= 2 * BSS);
#pragma unroll
        for (int mt = 0; mt < 4; mt++) {
            const int ibase = m0 + wm * 64 + mt * 16 + (lane >> 2);
#pragma unroll
            for (int half = 0; half < 2; half++) {
                const int i = ibase + half * 8;
                if (i >= SEQ) continue;
                const int mi = mask[b * SEQ + i];
                const float* srow = S + (long)(b * SEQ + i) * ND2 + (399 - i);
                const long obase = (long)b * SEQ * SEQ + (long)i * SEQ;
#pragma unroll
                for (int nt = 0; nt < 4; nt++) {
                    const int cc = n0 + wn * 32 + nt * 8 + (lane & 3) * 2;
#pragma unroll
                    for (int e = 0; e < 2; e++) {
                        const int j = cc + e;
                        if (j >= SEQ) continue;
                        const float v = (acc[mt][nt][half * 2 + e] + srow[j]) * 0.0625f;
                        out[obase + j] = v;
                        if (wmask) out[BSS + obase + j] = (float)(mi * mask[b * SEQ + j]);
                    }
                }
            }
        }
    }
}

extern "C" void kernel_launch(void* const* d_in, const int* in_sizes, int n_in,
                              void* d_out, int out_size)
{
    const float* x    = (const float*)d_in[0];  // (8,400,512)
    const int*   mask = (const int*)  d_in[1];  // (8,400)
    const float* w_q  = (const float*)d_in[2];  // (512,256)
    const float* w_q2 = (const float*)d_in[3];  // (512,256)
    const float* w_k  = (const float*)d_in[4];  // (512,256)
    const float* w_k2 = (const float*)d_in[5];  // (256,256)
    const float* rel  = (const float*)d_in[6];  // (1,400,400,256)
    float* out = (float*)d_out;

    float *Xt, *Wcat, *P, *RT, *S;
    cudaGetSymbolAddress((void**)&Xt,   g_Xt);
    cudaGetSymbolAddress((void**)&Wcat, g_Wcat);
    cudaGetSymbolAddress((void**)&P,    g_P);
    cudaGetSymbolAddress((void**)&RT,   g_RT);
    cudaGetSymbolAddress((void**)&S,    g_S);

    // 0) tf32-round x
    conv_x<<<(BS * SD / 4 + 255) / 256, 256>>>(x, Xt);

    // 1) Pack w_q, w_k (tf32) into Wcat
    pack_w<<<(SD * DM / 4 + 255) / 256, 256>>>(w_q, w_k, Wcat);

    // 2) W2 = w_q2 @ w_k2^T -> Wcat cols [512:768) (fp32 compute, tf32 store)
    w2gemm<<<dim3(DM / 64, SD / 64), 256>>>(w_q2, w_k2, Wcat);

    // 3) Relative table gather (tf32, padded to 896 cols)
    build_rt<<<ND2, DM>>>(rel, RT);

    // 4) P = Xt @ Wcat  (3200x768x512), output tf32-rounded
    mmaT<false, false, true><<<dim3(PW / 128, BS / 128), 256>>>(
        Xt, Wcat, P, BS, PW, SD, SD, PW, PW, 0, 0,
        nullptr, nullptr, nullptr, 0);

    // 5) S = P[:,512:768) @ RT  (3200x896x256), output fp32
    mmaT<false, false, false><<<dim3(ND2 / 128, BS / 128), 256>>>(
        P + SD, RT, S, BS, ND2, DM, PW, ND2, ND2, 0, 0,
        nullptr, nullptr, nullptr, 0);

    // 6) E = Q @ K^T fused with combine + mask, batched over z
    mmaT<true, true, false><<<dim3(4, 4, BATCH), 256>>>(
        P, P + DM, nullptr, SEQ, SEQ, DM, PW, PW, 0,
        (long)SEQ * PW, (long)SEQ * PW,
        S, mask, out, out_size);
}

// round 8
// speedup vs baseline: 2.1835x; 1.0070x over previous
#include <cuda_runtime.h>
#include <cstdint>

#define SEQ 400
#define BATCH 8
#define DM 256          // d_model
#define SD 512          // source_dim
#define PW 768          // packed projection width: [Q | K | Q2W]
#define ND2 896         // delta columns padded (799 real)
#define BS (BATCH*SEQ)          // 3200
#define BSS (BATCH*SEQ*SEQ)     // 1280000

// Scratch (device globals — no allocations allowed)
__device__ float g_Xt[BS*SD];        // tf32-rounded x              (3200x512)
__device__ float g_Wcat[SD*PW];      // [w_q | w_k | w_q2@w_k2^T]   (512x768) tf32
__device__ float g_P[BS*PW];         // Xt @ Wcat                   (3200x768) tf32
__device__ float g_RT[DM*ND2];       // R^T: [d][delta+399]         (256x896) tf32
__device__ float g_S[BS*ND2];        // P[:,512:768] @ RT           (3200x896) fp32

// ---------------------------------------------------------------------------
__device__ __forceinline__ float f2tf32(float f) {
    uint32_t u;
    asm("cvt.rna.tf32.f32 %0, %1;" : "=r"(u) : "f"(f));
    return __uint_as_float(u);
}

__device__ __forceinline__ void mma8(float c[4], const uint32_t a[4], const uint32_t b[2]) {
    asm volatile("mma.sync.aligned.m16n8k8.row.col.f32.tf32.tf32.f32 "
        "{%0,%1,%2,%3}, {%4,%5,%6,%7}, {%8,%9}, {%0,%1,%2,%3};"
        : "+f"(c[0]), "+f"(c[1]), "+f"(c[2]), "+f"(c[3])
        : "r"(a[0]), "r"(a[1]), "r"(a[2]), "r"(a[3]), "r"(b[0]), "r"(b[1]));
}

__device__ __forceinline__ void cpa16(uint32_t dst, const float* src, bool p) {
    asm volatile("cp.async.cg.shared.global [%0], [%1], 16, %2;"
                 :: "r"(dst), "l"(src), "r"(p ? 16 : 0));
}
__device__ __forceinline__ void cpa_commit() {
    asm volatile("cp.async.commit_group;");
}
__device__ __forceinline__ void cpa_wait0() {
    asm volatile("cp.async.wait_group 0;");
}

// ---------------------------------------------------------------------------
// Fused setup kernel — all sections independent, one launch, 256 threads:
//   S0: Xt = tf32(x)                                  blocks [0, 1600)
//   S1: Wcat[:, 0:512) = tf32([w_q | w_k])            blocks [1600, 1728)
//   S2: RT (smem-transposed gather, tf32)             blocks [1728, 1840)
//   S3: Wcat[:, 512:768) = tf32(w_q2 @ w_k2^T)        blocks [1840, 1872)
//   S4: out[BSS..2BSS) = mask outer product           blocks [1872, 3122)
// ---------------------------------------------------------------------------
#define SB0 1600
#define SB1 (SB0 + 128)
#define SB2 (SB1 + 112)
#define SB3 (SB2 + 32)
#define SB4 (SB3 + 1250)

__global__ __launch_bounds__(256)
void setup_all(const float* __restrict__ x,
               const float* __restrict__ wq, const float* __restrict__ wk,
               const float* __restrict__ wq2, const float* __restrict__ wk2,
               const float* __restrict__ rel, const int* __restrict__ mask,
               float* __restrict__ Xt, float* __restrict__ Wcat,
               float* __restrict__ RT, float* __restrict__ out, int out_size)
{
    __shared__ float sh[2176 * 2];   // 17408 B: fits S2 (32x65) and S3 (2x16x68x2)
    const int blk = blockIdx.x;
    const int tid = threadIdx.x;

    if (blk < SB0) {
        // ---- S0: tf32-round x
        const int idx = blk * 256 + tid;
        float4 v = ((const float4*)x)[idx];
        v.x = f2tf32(v.x); v.y = f2tf32(v.y); v.z = f2tf32(v.z); v.w = f2tf32(v.w);
        ((float4*)Xt)[idx] = v;
    } else if (blk < SB1) {
        // ---- S1: pack w_q, w_k
        const int idx = (blk - SB0) * 256 + tid;
        const int row = idx / (DM / 4);
        const int c4  = idx % (DM / 4);
        float4 q = ((const float4*)wq)[idx];
        float4 k = ((const float4*)wk)[idx];
        q.x = f2tf32(q.x); q.y = f2tf32(q.y); q.z = f2tf32(q.z); q.w = f2tf32(q.w);
        k.x = f2tf32(k.x); k.y = f2tf32(k.y); k.z = f2tf32(k.z); k.w = f2tf32(k.w);
        ((float4*)(Wcat + (long)row * PW))[c4] = q;
        ((float4*)(Wcat + (long)row * PW + DM))[c4] = k;
    } else if (blk < SB2) {
        // ---- S2: RT transposed gather. Tile: 32 m x 64 d, smem transpose.
        float (*t)[65] = (float(*)[65])sh;
        const int blk2 = blk - SB1;
        const int m0 = (blk2 % 28) * 32;
        const int d0 = (blk2 / 28) * 64;
        const int dl = tid & 63, mb = tid >> 6;      // load: 64 d-lanes x 4 m
#pragma unroll
        for (int it = 0; it < 8; it++) {
            const int ml = mb * 8 + it;
            const int m = m0 + ml;
            float v = 0.f;
            if (m <= 798) {
                const int delta = m - 399;
                const long off = (delta >= 0) ? (long)delta * DM
                                              : (long)(-delta) * SEQ * DM;
                v = f2tf32(rel[off + d0 + dl]);
            }
            t[ml][dl] = v;
        }
        __syncthreads();
        const int ml2 = tid & 31, db = tid >> 5;     // store: 32 m-lanes x 8 d
#pragma unroll
        for (int it = 0; it < 8; it++) {
            const int dl2 = db + it * 8;
            RT[(long)(d0 + dl2) * ND2 + m0 + ml2] = t[ml2][dl2];
        }
    } else if (blk < SB3) {
        // ---- S3: W2 = w_q2 @ w_k2^T -> Wcat cols [512:768), fp32 SIMT
        float (*As)[68] = (float(*)[68])sh;
        float (*Bs)[68] = (float(*)[68])(sh + 16 * 68);
        const int blk2 = blk - SB2;
        const int m0 = (blk2 >> 2) * 64, n0 = (blk2 & 3) * 64;
        const int tx = tid & 15, ty = tid >> 4;
        const int ar = tid >> 2, ak = (tid & 3) * 4;
        float acc[4][4] = {};
        for (int k0 = 0; k0 < DM; k0 += 16) {
            float4 v = *(const float4*)(wq2 + (long)(m0 + ar) * DM + k0 + ak);
            As[ak][ar] = v.x; As[ak+1][ar] = v.y; As[ak+2][ar] = v.z; As[ak+3][ar] = v.w;
            float4 w = *(const float4*)(wk2 + (long)(n0 + ar) * DM + k0 + ak);
            Bs[ak][ar] = w.x; Bs[ak+1][ar] = w.y; Bs[ak+2][ar] = w.z; Bs[ak+3][ar] = w.w;
            __syncthreads();
#pragma unroll
            for (int kk = 0; kk < 16; kk++) {
                const float4 a = *(const float4*)&As[kk][ty * 4];
                const float4 b = *(const float4*)&Bs[kk][tx * 4];
                acc[0][0]+=a.x*b.x; acc[0][1]+=a.x*b.y; acc[0][2]+=a.x*b.z; acc[0][3]+=a.x*b.w;
                acc[1][0]+=a.y*b.x; acc[1][1]+=a.y*b.y; acc[1][2]+=a.y*b.z; acc[1][3]+=a.y*b.w;
                acc[2][0]+=a.z*b.x; acc[2][1]+=a.z*b.y; acc[2][2]+=a.z*b.z; acc[2][3]+=a.z*b.w;
                acc[3][0]+=a.w*b.x; acc[3][1]+=a.w*b.y; acc[3][2]+=a.w*b.z; acc[3][3]+=a.w*b.w;
            }
            __syncthreads();
        }
#pragma unroll
        for (int r = 0; r < 4; r++)
#pragma unroll
            for (int c = 0; c < 4; c++)
                Wcat[(long)(m0 + ty*4 + r) * PW + SD + n0 + tx*4 + c] = f2tf32(acc[r][c]);
    } else if (blk < SB4) {
        // ---- S4: mask outer product into out[BSS..2BSS)
        if (out_size < 2 * BSS) return;
        const int i4 = (blk - SB3) * 256 + tid;
        const long idx = (long)i4 * 4;
        if (idx >= BSS) return;
        const int j = (int)(idx % SEQ);
        const int bi = (int)(idx / SEQ);
        const int i = bi % SEQ, b = bi / SEQ;
        const float mi = (float)mask[b * SEQ + i];
        float4 o;
        o.x = mi * mask[b * SEQ + j];
        o.y = mi * mask[b * SEQ + j + 1];
        o.z = mi * mask[b * SEQ + j + 2];
        o.w = mi * mask[b * SEQ + j + 3];
        *(float4*)&out[BSS + idx] = o;
    }
}

// ---------------------------------------------------------------------------
// tf32 tensor-core GEMM v3. 128x128 block, BK=16, 128 threads (4 warps,
// each warp 64x64 via 4x8 m16n8k8 tiles -> 64 mma per 48 LDS.32 per ktile).
// Inputs pre-rounded to tf32. cp.async double-buffered, padded row-major
// smem (A pad 20, B-NN pad 136, B-NT pad 20; all access patterns
// conflict-free).
//
// NTB=false: C = A[M,K] @ B[K,N]; requires M%128==0, N%128==0.
// NTB=true : C = A[M,K] @ B[N,K]^T; M,N bounded by Mreal/Nreal (zfill).
// ECOMB: fused epilogue out = (acc + gather(S))/16 (mask handled in setup).
// OTF: tf32-round C on store.
// ---------------------------------------------------------------------------
template <bool NTB, bool ECOMB, bool OTF>
__global__ __launch_bounds__(128)
void mmaT(const float* __restrict__ A, const float* __restrict__ B,
          float* __restrict__ C,
          int Mreal, int Nreal, int K, int lda, int ldb, int ldc,
          long sA, long sB,
          const float* __restrict__ S, float* __restrict__ out, int out_size)
{
    constexpr int BR = NTB ? 128 : 16;
    constexpr int BC = NTB ? 20 : 136;
    __shared__ float As[2][128][20];
    __shared__ float Bs[2][BR][BC];

    const int tid  = threadIdx.x;
    const int lane = tid & 31;
    const int wid  = tid >> 5;      // 0..3
    const int wm   = wid >> 1;      // 0..1
    const int wn   = wid & 1;       // 0..1
    const int m0   = blockIdx.y * 128;
    const int n0   = blockIdx.x * 128;

    A += blockIdx.z * sA;
    B += blockIdx.z * sB;

    const uint32_t uA = (uint32_t)__cvta_generic_to_shared(&As[0][0][0]);
    const uint32_t uB = (uint32_t)__cvta_generic_to_shared(&Bs[0][0][0]);

    // ---- A loader: thread t owns row t, 4 float4s covering 16 k
    const bool aok = (m0 + tid) < Mreal;
    const float* aptr = A + (long)(aok ? (m0 + tid) : 0) * lda;
    const uint32_t adst = uA + (uint32_t)(tid * 20) * 4;

    // ---- B loader
    const float* bptr;
    uint32_t bdst;
    bool bok = true;
    if (NTB) {
        bok  = (n0 + tid) < Nreal;
        bptr = B + (long)(bok ? (n0 + tid) : 0) * ldb;
        bdst = uB + (uint32_t)(tid * 20) * 4;
    } else {
        const int brow = tid >> 3;          // 0..15
        const int bcol = (tid & 7) * 16;    // 0..112
        bptr = B + (long)brow * ldb + n0 + bcol;
        bdst = uB + (uint32_t)(brow * BC + bcol) * 4;
    }

    float acc[4][8][4];
#pragma unroll
    for (int mt = 0; mt < 4; mt++)
#pragma unroll
        for (int nt = 0; nt < 8; nt++)
#pragma unroll
            for (int r = 0; r < 4; r++) acc[mt][nt][r] = 0.f;

    auto load_stage = [&](int buf, int k0) {
        const uint32_t ao = (uint32_t)buf * (128 * 20 * 4);
        const uint32_t bo = (uint32_t)buf * (BR * BC * 4);
#pragma unroll
        for (int q = 0; q < 4; q++)
            cpa16(adst + ao + q * 16, aptr + k0 + q * 4, aok);
        if (NTB) {
#pragma unroll
            for (int q = 0; q < 4; q++)
                cpa16(bdst + bo + q * 16, bptr + k0 + q * 4, bok);
        } else {
#pragma unroll
            for (int q = 0; q < 4; q++)
                cpa16(bdst + bo + q * 16, bptr + (long)k0 * ldb + q * 4, true);
        }
        cpa_commit();
    };

    load_stage(0, 0);
    cpa_wait0();
    __syncthreads();

    const int nk = K >> 4;
    int buf = 0;
    for (int kt = 0; kt < nk; kt++) {
        const bool more = (kt + 1 < nk);
        if (more) load_stage(buf ^ 1, (kt + 1) << 4);

#pragma unroll
        for (int h = 0; h < 2; h++) {
            const int c = h * 8 + (lane & 3);
            uint32_t af[4][4];
            uint32_t bf[8][2];
            const float* abase = &As[buf][wm * 64 + (lane >> 2)][c];
#pragma unroll
            for (int mt = 0; mt < 4; mt++) {
                af[mt][0] = __float_as_uint(abase[(mt * 16    ) * 20    ]);
                af[mt][1] = __float_as_uint(abase[(mt * 16 + 8) * 20    ]);
                af[mt][2] = __float_as_uint(abase[(mt * 16    ) * 20 + 4]);
                af[mt][3] = __float_as_uint(abase[(mt * 16 + 8) * 20 + 4]);
            }
#pragma unroll
            for (int nt = 0; nt < 8; nt++) {
                const int nB = wn * 64 + nt * 8 + (lane >> 2);
                if (NTB) {
                    bf[nt][0] = __float_as_uint(Bs[buf][nB][c]);
                    bf[nt][1] = __float_as_uint(Bs[buf][nB][c + 4]);
                } else {
                    bf[nt][0] = __float_as_uint(Bs[buf][c][nB]);
                    bf[nt][1] = __float_as_uint(Bs[buf][c + 4][nB]);
                }
            }
#pragma unroll
            for (int mt = 0; mt < 4; mt++)
#pragma unroll
                for (int nt = 0; nt < 8; nt++)
                    mma8(acc[mt][nt], af[mt], bf[nt]);
        }

        if (more) {
            cpa_wait0();
            __syncthreads();
            buf ^= 1;
        }
    }

    // ---- epilogue ----
    if (!ECOMB) {
#pragma unroll
        for (int mt = 0; mt < 4; mt++) {
            const int r0 = m0 + wm * 64 + mt * 16 + (lane >> 2);
            const int r1 = r0 + 8;
#pragma unroll
            for (int nt = 0; nt < 8; nt++) {
                const int cc = n0 + wn * 64 + nt * 8 + (lane & 3) * 2;
                float v0 = acc[mt][nt][0], v1 = acc[mt][nt][1];
                float v2 = acc[mt][nt][2], v3 = acc[mt][nt][3];
                if (OTF) { v0 = f2tf32(v0); v1 = f2tf32(v1); v2 = f2tf32(v2); v3 = f2tf32(v3); }
                *(float2*)&C[(long)r0 * ldc + cc] = make_float2(v0, v1);
                *(float2*)&C[(long)r1 * ldc + cc] = make_float2(v2, v3);
            }
        }
    } else {
        const int b = blockIdx.z;
#pragma unroll
        for (int mt = 0; mt < 4; mt++) {
            const int ibase = m0 + wm * 64 + mt * 16 + (lane >> 2);
#pragma unroll
            for (int half = 0; half < 2; half++) {
                const int i = ibase + half * 8;
                if (i >= SEQ) continue;
                const float* srow = S + (long)(b * SEQ + i) * ND2 + (399 - i);
                const long obase = (long)b * SEQ * SEQ + (long)i * SEQ;
#pragma unroll
                for (int nt = 0; nt < 8; nt++) {
                    const int cc = n0 + wn * 64 + nt * 8 + (lane & 3) * 2;
#pragma unroll
                    for (int e = 0; e < 2; e++) {
                        const int j = cc + e;
                        if (j >= SEQ) continue;
                        out[obase + j] = (acc[mt][nt][half * 2 + e] + srow[j]) * 0.0625f;
                    }
                }
            }
        }
    }
}

extern "C" void kernel_launch(void* const* d_in, const int* in_sizes, int n_in,
                              void* d_out, int out_size)
{
    const float* x    = (const float*)d_in[0];  // (8,400,512)
    const int*   mask = (const int*)  d_in[1];  // (8,400)
    const float* w_q  = (const float*)d_in[2];  // (512,256)
    const float* w_q2 = (const float*)d_in[3];  // (512,256)
    const float* w_k  = (const float*)d_in[4];  // (512,256)
    const float* w_k2 = (const float*)d_in[5];  // (256,256)
    const float* rel  = (const float*)d_in[6];  // (1,400,400,256)
    float* out = (float*)d_out;

    float *Xt, *Wcat, *P, *RT, *S;
    cudaGetSymbolAddress((void**)&Xt,   g_Xt);
    cudaGetSymbolAddress((void**)&Wcat, g_Wcat);
    cudaGetSymbolAddress((void**)&P,    g_P);
    cudaGetSymbolAddress((void**)&RT,   g_RT);
    cudaGetSymbolAddress((void**)&S,    g_S);

    // 1) All setup in one launch (Xt, Wcat, RT, mask half of out)
    setup_all<<<SB4, 256>>>(x, w_q, w_k, w_q2, w_k2, rel, mask,
                            Xt, Wcat, RT, out, out_size);

    // 2) P = Xt @ Wcat  (3200x768x512), output tf32-rounded
    mmaT<false, false, true><<<dim3(PW / 128, BS / 128), 128>>>(
        Xt, Wcat, P, BS, PW, SD, SD, PW, PW, 0, 0, nullptr, nullptr, 0);

    // 3) S = P[:,512:768) @ RT  (3200x896x256), output fp32
    mmaT<false, false, false><<<dim3(ND2 / 128, BS / 128), 128>>>(
        P + SD, RT, S, BS, ND2, DM, PW, ND2, ND2, 0, 0, nullptr, nullptr, 0);

    // 4) E = Q @ K^T fused with combine, batched over z
    mmaT<true, true, false><<<dim3(4, 4, BATCH), 128>>>(
        P, P + DM, nullptr, SEQ, SEQ, DM, PW, PW, 0,
        (long)SEQ * PW, (long)SEQ * PW, S, out, out_size);
}

// round 9
// speedup vs baseline: 2.7667x; 1.2671x over previous
#include <cuda_runtime.h>
#include <cstdint>

#define SEQ 400
#define BATCH 8
#define DM 256          // d_model
#define SD 512          // source_dim
#define PW 768          // packed projection width: [Q | K | Q2W]
#define ND2 896         // delta columns padded (799 real)
#define BS (BATCH*SEQ)          // 3200
#define BSS (BATCH*SEQ*SEQ)     // 1280000

// Scratch (device globals — no allocations allowed)
__device__ float g_Xt[BS*SD];        // tf32-rounded x              (3200x512)
__device__ float g_Wcat[SD*PW];      // [w_q | w_k | w_q2@w_k2^T]   (512x768) tf32
__device__ float g_P[BS*PW];         // Xt @ Wcat                   (3200x768) tf32
__device__ float g_RT[DM*ND2];       // R^T: [d][delta+399]         (256x896) tf32
__device__ float g_S[BS*ND2];        // P[:,512:768] @ RT           (3200x896) fp32

// ---------------------------------------------------------------------------
__device__ __forceinline__ float f2tf32(float f) {
    uint32_t u;
    asm("cvt.rna.tf32.f32 %0, %1;" : "=r"(u) : "f"(f));
    return __uint_as_float(u);
}

__device__ __forceinline__ void mma8(float c[4], const uint32_t a[4], const uint32_t b[2]) {
    asm volatile("mma.sync.aligned.m16n8k8.row.col.f32.tf32.tf32.f32 "
        "{%0,%1,%2,%3}, {%4,%5,%6,%7}, {%8,%9}, {%0,%1,%2,%3};"
        : "+f"(c[0]), "+f"(c[1]), "+f"(c[2]), "+f"(c[3])
        : "r"(a[0]), "r"(a[1]), "r"(a[2]), "r"(a[3]), "r"(b[0]), "r"(b[1]));
}

__device__ __forceinline__ void cpa16(uint32_t dst, const float* src, bool p) {
    asm volatile("cp.async.cg.shared.global [%0], [%1], 16, %2;"
                 :: "r"(dst), "l"(src), "r"(p ? 16 : 0));
}
__device__ __forceinline__ void cpa_commit() {
    asm volatile("cp.async.commit_group;");
}
__device__ __forceinline__ void cpa_wait0() {
    asm volatile("cp.async.wait_group 0;");
}

// ---------------------------------------------------------------------------
// Fused setup kernel — all sections independent, one launch, 256 threads:
//   S0: Xt = tf32(x)                                  blocks [0, 1600)
//   S1: Wcat[:, 0:512) = tf32([w_q | w_k])            blocks [1600, 1728)
//   S2: RT (smem-transposed gather, tf32)             blocks [1728, 1840)
//   S3: Wcat[:, 512:768) = tf32(w_q2 @ w_k2^T)        blocks [1840, 1872)
//   S4: out[BSS..2BSS) = mask outer product           blocks [1872, 3122)
// ---------------------------------------------------------------------------
#define SB0 1600
#define SB1 (SB0 + 128)
#define SB2 (SB1 + 112)
#define SB3 (SB2 + 32)
#define SB4 (SB3 + 1250)

__global__ __launch_bounds__(256)
void setup_all(const float* __restrict__ x,
               const float* __restrict__ wq, const float* __restrict__ wk,
               const float* __restrict__ wq2, const float* __restrict__ wk2,
               const float* __restrict__ rel, const int* __restrict__ mask,
               float* __restrict__ Xt, float* __restrict__ Wcat,
               float* __restrict__ RT, float* __restrict__ out, int out_size)
{
    __shared__ float sh[2176 * 2];   // 17408 B: fits S2 (32x65) and S3 (2x16x68)
    const int blk = blockIdx.x;
    const int tid = threadIdx.x;

    if (blk < SB0) {
        // ---- S0: tf32-round x
        const int idx = blk * 256 + tid;
        float4 v = ((const float4*)x)[idx];
        v.x = f2tf32(v.x); v.y = f2tf32(v.y); v.z = f2tf32(v.z); v.w = f2tf32(v.w);
        ((float4*)Xt)[idx] = v;
    } else if (blk < SB1) {
        // ---- S1: pack w_q, w_k
        const int idx = (blk - SB0) * 256 + tid;
        const int row = idx / (DM / 4);
        const int c4  = idx % (DM / 4);
        float4 q = ((const float4*)wq)[idx];
        float4 k = ((const float4*)wk)[idx];
        q.x = f2tf32(q.x); q.y = f2tf32(q.y); q.z = f2tf32(q.z); q.w = f2tf32(q.w);
        k.x = f2tf32(k.x); k.y = f2tf32(k.y); k.z = f2tf32(k.z); k.w = f2tf32(k.w);
        ((float4*)(Wcat + (long)row * PW))[c4] = q;
        ((float4*)(Wcat + (long)row * PW + DM))[c4] = k;
    } else if (blk < SB2) {
        // ---- S2: RT transposed gather. Tile: 32 m x 64 d, smem transpose.
        float (*t)[65] = (float(*)[65])sh;
        const int blk2 = blk - SB1;
        const int m0 = (blk2 % 28) * 32;
        const int d0 = (blk2 / 28) * 64;
        const int dl = tid & 63, mb = tid >> 6;      // load: 64 d-lanes x 4 m
#pragma unroll
        for (int it = 0; it < 8; it++) {
            const int ml = mb * 8 + it;
            const int m = m0 + ml;
            float v = 0.f;
            if (m <= 798) {
                const int delta = m - 399;
                const long off = (delta >= 0) ? (long)delta * DM
                                              : (long)(-delta) * SEQ * DM;
                v = f2tf32(rel[off + d0 + dl]);
            }
            t[ml][dl] = v;
        }
        __syncthreads();
        const int ml2 = tid & 31, db = tid >> 5;     // store: 32 m-lanes x 8 d
#pragma unroll
        for (int it = 0; it < 8; it++) {
            const int dl2 = db + it * 8;
            RT[(long)(d0 + dl2) * ND2 + m0 + ml2] = t[ml2][dl2];
        }
    } else if (blk < SB3) {
        // ---- S3: W2 = w_q2 @ w_k2^T -> Wcat cols [512:768), fp32 SIMT
        float (*As)[68] = (float(*)[68])sh;
        float (*Bs)[68] = (float(*)[68])(sh + 16 * 68);
        const int blk2 = blk - SB2;
        const int m0 = (blk2 >> 2) * 64, n0 = (blk2 & 3) * 64;
        const int tx = tid & 15, ty = tid >> 4;
        const int ar = tid >> 2, ak = (tid & 3) * 4;
        float acc[4][4] = {};
        for (int k0 = 0; k0 < DM; k0 += 16) {
            float4 v = *(const float4*)(wq2 + (long)(m0 + ar) * DM + k0 + ak);
            As[ak][ar] = v.x; As[ak+1][ar] = v.y; As[ak+2][ar] = v.z; As[ak+3][ar] = v.w;
            float4 w = *(const float4*)(wk2 + (long)(n0 + ar) * DM + k0 + ak);
            Bs[ak][ar] = w.x; Bs[ak+1][ar] = w.y; Bs[ak+2][ar] = w.z; Bs[ak+3][ar] = w.w;
            __syncthreads();
#pragma unroll
            for (int kk = 0; kk < 16; kk++) {
                const float4 a = *(const float4*)&As[kk][ty * 4];
                const float4 b = *(const float4*)&Bs[kk][tx * 4];
                acc[0][0]+=a.x*b.x; acc[0][1]+=a.x*b.y; acc[0][2]+=a.x*b.z; acc[0][3]+=a.x*b.w;
                acc[1][0]+=a.y*b.x; acc[1][1]+=a.y*b.y; acc[1][2]+=a.y*b.z; acc[1][3]+=a.y*b.w;
                acc[2][0]+=a.z*b.x; acc[2][1]+=a.z*b.y; acc[2][2]+=a.z*b.z; acc[2][3]+=a.z*b.w;
                acc[3][0]+=a.w*b.x; acc[3][1]+=a.w*b.y; acc[3][2]+=a.w*b.z; acc[3][3]+=a.w*b.w;
            }
            __syncthreads();
        }
#pragma unroll
        for (int r = 0; r < 4; r++)
#pragma unroll
            for (int c = 0; c < 4; c++)
                Wcat[(long)(m0 + ty*4 + r) * PW + SD + n0 + tx*4 + c] = f2tf32(acc[r][c]);
    } else if (blk < SB4) {
        // ---- S4: mask outer product into out[BSS..2BSS)
        if (out_size < 2 * BSS) return;
        const int i4 = (blk - SB3) * 256 + tid;
        const long idx = (long)i4 * 4;
        if (idx >= BSS) return;
        const int j = (int)(idx % SEQ);
        const int bi = (int)(idx / SEQ);
        const int i = bi % SEQ, b = bi / SEQ;
        const float mi = (float)mask[b * SEQ + i];
        float4 o;
        o.x = mi * mask[b * SEQ + j];
        o.y = mi * mask[b * SEQ + j + 1];
        o.z = mi * mask[b * SEQ + j + 2];
        o.w = mi * mask[b * SEQ + j + 3];
        *(float4*)&out[BSS + idx] = o;
    }
}

// ---------------------------------------------------------------------------
// tf32 tensor-core GEMM v4. 128x128 block, BK=16, 256 threads (8 warps,
// 64x32 warp tiles, 4x4 m16n8k8). cp.async double-buffered; all smem store
// and fragment-load bank patterns verified conflict-free (A/B-NT rows pad
// 20 with the 20-stride permutation covering all 32 banks; B-NN rows pad
// 136 with sequential quads).
//
// NTB=false: C = A[M,K] @ B[K,N]; requires M%128==0, N%128==0.
// NTB=true : C = A[M,K] @ B[N,K]^T; M,N bounded by Mreal/Nreal (zfill).
// ECOMB: fused epilogue out = (acc + gather(S))/16 (mask handled in setup).
// OTF: tf32-round C on store.
// ---------------------------------------------------------------------------
template <bool NTB, bool ECOMB, bool OTF>
__global__ __launch_bounds__(256)
void mmaT(const float* __restrict__ A, const float* __restrict__ B,
          float* __restrict__ C,
          int Mreal, int Nreal, int K, int lda, int ldb, int ldc,
          long sA, long sB,
          const float* __restrict__ S, float* __restrict__ out, int out_size)
{
    constexpr int BR = NTB ? 128 : 16;
    constexpr int BC = NTB ? 20 : 136;
    __shared__ float As[2][128][20];
    __shared__ float Bs[2][BR][BC];

    const int tid  = threadIdx.x;
    const int lane = tid & 31;
    const int wid  = tid >> 5;      // 0..7
    const int wm   = wid >> 2;      // 0..1
    const int wn   = wid & 3;       // 0..3
    const int m0   = blockIdx.y * 128;
    const int n0   = blockIdx.x * 128;

    A += blockIdx.z * sA;
    B += blockIdx.z * sB;

    const uint32_t uA = (uint32_t)__cvta_generic_to_shared(&As[0][0][0]);
    const uint32_t uB = (uint32_t)__cvta_generic_to_shared(&Bs[0][0][0]);

    // ---- A loader: quads tid and tid+256; row=q>>2, kq=(q&3)*4.
    const int ar1 = tid >> 2;            // 0..63
    const int ar2 = ar1 + 64;            // 64..127
    const int akq = (tid & 3) * 4;       // 0,4,8,12
    const bool aok1 = (m0 + ar1) < Mreal;
    const bool aok2 = (m0 + ar2) < Mreal;
    const float* aptr1 = A + (long)(aok1 ? (m0 + ar1) : 0) * lda + akq;
    const float* aptr2 = A + (long)(aok2 ? (m0 + ar2) : 0) * lda + akq;
    const uint32_t adst1 = uA + (uint32_t)(ar1 * 20 + akq) * 4;
    const uint32_t adst2 = uA + (uint32_t)(ar2 * 20 + akq) * 4;

    // ---- B loader
    const float *bptr1, *bptr2;
    uint32_t bdst1, bdst2;
    bool bok1 = true, bok2 = true;
    if (NTB) {
        const int br1 = tid >> 2, br2 = br1 + 64;
        bok1 = (n0 + br1) < Nreal;
        bok2 = (n0 + br2) < Nreal;
        bptr1 = B + (long)(bok1 ? (n0 + br1) : 0) * ldb + akq;
        bptr2 = B + (long)(bok2 ? (n0 + br2) : 0) * ldb + akq;
        bdst1 = uB + (uint32_t)(br1 * 20 + akq) * 4;
        bdst2 = uB + (uint32_t)(br2 * 20 + akq) * 4;
    } else {
        const int brow = tid >> 5;          // 0..7 (second: +8)
        const int bcol = (tid & 31) * 4;    // 0..124
        bptr1 = B + (long)brow * ldb + n0 + bcol;
        bptr2 = B + (long)(brow + 8) * ldb + n0 + bcol;
        bdst1 = uB + (uint32_t)(brow * BC + bcol) * 4;
        bdst2 = uB + (uint32_t)((brow + 8) * BC + bcol) * 4;
    }

    float acc[4][4][4];
#pragma unroll
    for (int mt = 0; mt < 4; mt++)
#pragma unroll
        for (int nt = 0; nt < 4; nt++)
#pragma unroll
            for (int r = 0; r < 4; r++) acc[mt][nt][r] = 0.f;

    auto load_stage = [&](int buf, int k0) {
        const uint32_t ao = (uint32_t)buf * (128 * 20 * 4);
        const uint32_t bo = (uint32_t)buf * (BR * BC * 4);
        cpa16(adst1 + ao, aptr1 + k0, aok1);
        cpa16(adst2 + ao, aptr2 + k0, aok2);
        if (NTB) {
            cpa16(bdst1 + bo, bptr1 + k0, bok1);
            cpa16(bdst2 + bo, bptr2 + k0, bok2);
        } else {
            cpa16(bdst1 + bo, bptr1 + (long)k0 * ldb, true);
            cpa16(bdst2 + bo, bptr2 + (long)k0 * ldb, true);
        }
        cpa_commit();
    };

    load_stage(0, 0);
    cpa_wait0();
    __syncthreads();

    const int nk = K >> 4;
    int buf = 0;
    for (int kt = 0; kt < nk; kt++) {
        const bool more = (kt + 1 < nk);
        if (more) load_stage(buf ^ 1, (kt + 1) << 4);

#pragma unroll
        for (int h = 0; h < 2; h++) {
            const int c = h * 8 + (lane & 3);
            uint32_t af[4][4];
            uint32_t bf[4][2];
            const float* abase = &As[buf][wm * 64 + (lane >> 2)][c];
#pragma unroll
            for (int mt = 0; mt < 4; mt++) {
                af[mt][0] = __float_as_uint(abase[(mt * 16    ) * 20    ]);
                af[mt][1] = __float_as_uint(abase[(mt * 16 + 8) * 20    ]);
                af[mt][2] = __float_as_uint(abase[(mt * 16    ) * 20 + 4]);
                af[mt][3] = __float_as_uint(abase[(mt * 16 + 8) * 20 + 4]);
            }
#pragma unroll
            for (int nt = 0; nt < 4; nt++) {
                const int nB = wn * 32 + nt * 8 + (lane >> 2);
                if (NTB) {
                    bf[nt][0] = __float_as_uint(Bs[buf][nB][c]);
                    bf[nt][1] = __float_as_uint(Bs[buf][nB][c + 4]);
                } else {
                    bf[nt][0] = __float_as_uint(Bs[buf][c][nB]);
                    bf[nt][1] = __float_as_uint(Bs[buf][c + 4][nB]);
                }
            }
#pragma unroll
            for (int mt = 0; mt < 4; mt++)
#pragma unroll
                for (int nt = 0; nt < 4; nt++)
                    mma8(acc[mt][nt], af[mt], bf[nt]);
        }

        if (more) {
            cpa_wait0();
            __syncthreads();
            buf ^= 1;
        }
    }

    // ---- epilogue ----
    if (!ECOMB) {
#pragma unroll
        for (int mt = 0; mt < 4; mt++) {
            const int r0 = m0 + wm * 64 + mt * 16 + (lane >> 2);
            const int r1 = r0 + 8;
#pragma unroll
            for (int nt = 0; nt < 4; nt++) {
                const int cc = n0 + wn * 32 + nt * 8 + (lane & 3) * 2;
                float v0 = acc[mt][nt][0], v1 = acc[mt][nt][1];
                float v2 = acc[mt][nt][2], v3 = acc[mt][nt][3];
                if (OTF) { v0 = f2tf32(v0); v1 = f2tf32(v1); v2 = f2tf32(v2); v3 = f2tf32(v3); }
                *(float2*)&C[(long)r0 * ldc + cc] = make_float2(v0, v1);
                *(float2*)&C[(long)r1 * ldc + cc] = make_float2(v2, v3);
            }
        }
    } else {
        const int b = blockIdx.z;
#pragma unroll
        for (int mt = 0; mt < 4; mt++) {
            const int ibase = m0 + wm * 64 + mt * 16 + (lane >> 2);
#pragma unroll
            for (int half = 0; half < 2; half++) {
                const int i = ibase + half * 8;
                if (i >= SEQ) continue;
                const float* srow = S + (long)(b * SEQ + i) * ND2 + (399 - i);
                const long obase = (long)b * SEQ * SEQ + (long)i * SEQ;
#pragma unroll
                for (int nt = 0; nt < 4; nt++) {
                    const int cc = n0 + wn * 32 + nt * 8 + (lane & 3) * 2;
                    if (cc >= SEQ) continue;   // cc even, so cc+1 <= 399
                    const float v0 = (acc[mt][nt][half * 2 + 0] + srow[cc])     * 0.0625f;
                    const float v1 = (acc[mt][nt][half * 2 + 1] + srow[cc + 1]) * 0.0625f;
                    *(float2*)&out[obase + cc] = make_float2(v0, v1);
                }
            }
        }
    }
}

extern "C" void kernel_launch(void* const* d_in, const int* in_sizes, int n_in,
                              void* d_out, int out_size)
{
    const float* x    = (const float*)d_in[0];  // (8,400,512)
    const int*   mask = (const int*)  d_in[1];  // (8,400)
    const float* w_q  = (const float*)d_in[2];  // (512,256)
    const float* w_q2 = (const float*)d_in[3];  // (512,256)
    const float* w_k  = (const float*)d_in[4];  // (512,256)
    const float* w_k2 = (const float*)d_in[5];  // (256,256)
    const float* rel  = (const float*)d_in[6];  // (1,400,400,256)
    float* out = (float*)d_out;

    float *Xt, *Wcat, *P, *RT, *S;
    cudaGetSymbolAddress((void**)&Xt,   g_Xt);
    cudaGetSymbolAddress((void**)&Wcat, g_Wcat);
    cudaGetSymbolAddress((void**)&P,    g_P);
    cudaGetSymbolAddress((void**)&RT,   g_RT);
    cudaGetSymbolAddress((void**)&S,    g_S);

    // 1) All setup in one launch (Xt, Wcat, RT, mask half of out)
    setup_all<<<SB4, 256>>>(x, w_q, w_k, w_q2, w_k2, rel, mask,
                            Xt, Wcat, RT, out, out_size);

    // 2) P = Xt @ Wcat  (3200x768x512), output tf32-rounded
    mmaT<false, false, true><<<dim3(PW / 128, BS / 128), 256>>>(
        Xt, Wcat, P, BS, PW, SD, SD, PW, PW, 0, 0, nullptr, nullptr, 0);

    // 3) S = P[:,512:768) @ RT  (3200x896x256), output fp32
    mmaT<false, false, false><<<dim3(ND2 / 128, BS / 128), 256>>>(
        P + SD, RT, S, BS, ND2, DM, PW, ND2, ND2, 0, 0, nullptr, nullptr, 0);

    // 4) E = Q @ K^T fused with combine, batched over z
    mmaT<true, true, false><<<dim3(4, 4, BATCH), 256>>>(
        P, P + DM, nullptr, SEQ, SEQ, DM, PW, PW, 0,
        (long)SEQ * PW, (long)SEQ * PW, S, out, out_size);
}